// round 2
// baseline (speedup 1.0000x reference)
#include <cuda_runtime.h>
#include <cuda_bf16.h>
#include <cstdint>

#define B_   64
#define N_   5000
#define NP1  5001
#define D_   128
#define TILES 40            // ceil(5000/128)
#define WSTRIDE 76          // smem weight row stride (words): 76%32=12 -> conflict-free

// ------------------------- device scratch (no allocs) -----------------------
__device__ float    g_W1f[128 * 512];     // fused fp32 weights [n][512]
__device__ uint32_t g_Whi[128 * 256];     // bf16 hi pairs [n][k2]
__device__ uint32_t g_Wlo[128 * 256];     // bf16 lo pairs
__device__ float    g_partS[B_ * TILES * D_];
__device__ float    g_partQ[B_ * TILES * D_];
__device__ float    g_mean[B_ * D_];
__device__ float    g_rstd[B_ * D_];

// ------------------------------- helpers ------------------------------------
__device__ __forceinline__ void split2(float x, float y, uint32_t& hi, uint32_t& lo) {
    __nv_bfloat162 h = __floats2bfloat162_rn(x, y);
    float lx = x - __bfloat162float(h.x);
    float ly = y - __bfloat162float(h.y);
    __nv_bfloat162 l = __floats2bfloat162_rn(lx, ly);
    hi = *reinterpret_cast<uint32_t*>(&h);
    lo = *reinterpret_cast<uint32_t*>(&l);
}

__device__ __forceinline__ void mma16816(float (&c)[4],
                                         uint32_t a0, uint32_t a1, uint32_t a2, uint32_t a3,
                                         uint32_t b0, uint32_t b1) {
    asm("mma.sync.aligned.m16n8k16.row.col.f32.bf16.bf16.f32 "
        "{%0,%1,%2,%3}, {%4,%5,%6,%7}, {%8,%9}, {%0,%1,%2,%3};"
        : "+f"(c[0]), "+f"(c[1]), "+f"(c[2]), "+f"(c[3])
        : "r"(a0), "r"(a1), "r"(a2), "r"(a3), "r"(b0), "r"(b1));
}

// -------------------------- weight prep kernels ------------------------------
__global__ void prep1_kernel(const float* __restrict__ w_comb,
                             const float* __restrict__ w_left,
                             const float* __restrict__ w_right,
                             const float* __restrict__ w_ff) {
    int n = blockIdx.x, k = threadIdx.x;          // 128 x 128
    float* row = g_W1f + n * 512;
    row[k] = w_comb[n * 256 + k];
    float a1 = 0.f, a2 = 0.f;
    for (int m = 0; m < 128; ++m) {
        float wc = w_comb[n * 256 + 128 + m];
        a1 = fmaf(wc, w_left[m * 128 + k], a1);
        a2 = fmaf(wc, w_right[m * 128 + k], a2);
    }
    row[128 + k] = a1;
    row[256 + k] = a2;
    row[384 + k] = w_ff[n * 128 + k];
}

__global__ void prep2_kernel() {
    int n = blockIdx.x, k2 = threadIdx.x;         // 128 x 256
    float2 x = *reinterpret_cast<const float2*>(g_W1f + n * 512 + 2 * k2);
    uint32_t hi, lo;
    split2(x.x, x.y, hi, lo);
    g_Whi[n * 256 + k2] = hi;
    g_Wlo[n * 256 + k2] = lo;
}

// --------------------------- main fused kernel -------------------------------
// smem layout (words): sWhi[128*76] | sWlo[128*76] | sBc[128] | sBf[128] | sS[8*128] | sQ[8*128]
#define SMEM_WORDS (2 * 128 * WSTRIDE + 128 + 128 + 2 * 8 * 128)
#define SMEM_BYTES (SMEM_WORDS * 4)

__global__ void __launch_bounds__(256, 1)
main_kernel(const int* __restrict__ sn, const float* __restrict__ emb,
            const float* __restrict__ b_comb, const float* __restrict__ b_ff,
            float* __restrict__ out) {
    extern __shared__ uint32_t smem[];
    uint32_t* sWhi = smem;
    uint32_t* sWlo = smem + 128 * WSTRIDE;
    float* sBc = reinterpret_cast<float*>(smem + 2 * 128 * WSTRIDE);
    float* sBf = sBc + 128;
    float* sS  = sBf + 128;
    float* sQ  = sS + 8 * 128;

    const int tid  = threadIdx.x;
    const int w    = tid >> 5;
    const int lane = tid & 31;
    const int g    = lane >> 2;
    const int cq   = lane & 3;
    const int b    = blockIdx.y;

    const int tokBase = blockIdx.x * 128 + w * 16;
    const int t0 = tokBase + g;
    const int t1 = t0 + 8;
    const bool v0 = (t0 < N_), v1 = (t1 < N_);
    const int t0c = v0 ? t0 : (N_ - 1);
    const int t1c = v1 ? t1 : (N_ - 1);

    const float* emb_b = emb + (size_t)b * NP1 * D_;
    const int*   sn_b  = sn  + (size_t)b * N_ * 2;

    if (tid < 128) sBc[tid] = b_comb[tid];
    else           sBf[tid - 128] = b_ff[tid - 128];

    float acc[16][4];
#pragma unroll
    for (int j = 0; j < 16; ++j) { acc[j][0]=0.f; acc[j][1]=0.f; acc[j][2]=0.f; acc[j][3]=0.f; }

    // ---- Stage 1: h_pre = [cust | left | right] @ W1^T  (3 x K=128 slices) ----
    for (int s = 0; s < 3; ++s) {
        __syncthreads();
        for (int i = tid; i < 2048; i += 256) {
            int n = i >> 4, cc = (i & 15) << 2;
            *reinterpret_cast<uint4*>(&sWhi[n * WSTRIDE + cc]) =
                *reinterpret_cast<const uint4*>(&g_Whi[n * 256 + s * 64 + cc]);
            *reinterpret_cast<uint4*>(&sWlo[n * WSTRIDE + cc]) =
                *reinterpret_cast<const uint4*>(&g_Wlo[n * 256 + s * 64 + cc]);
        }
        __syncthreads();

        int i0, i1;
        if (s == 0) { i0 = 1 + t0c; i1 = 1 + t1c; }
        else        { i0 = sn_b[t0c * 2 + (s - 1)]; i1 = sn_b[t1c * 2 + (s - 1)]; }
        const float* p0 = emb_b + (size_t)i0 * D_;
        const float* p1 = emb_b + (size_t)i1 * D_;

        for (int c = 0; c < 8; ++c) {
            const int kc = c * 16 + cq * 2;
            float2 x0a = *reinterpret_cast<const float2*>(p0 + kc);
            float2 x0b = *reinterpret_cast<const float2*>(p0 + kc + 8);
            float2 x1a = *reinterpret_cast<const float2*>(p1 + kc);
            float2 x1b = *reinterpret_cast<const float2*>(p1 + kc + 8);
            uint32_t ah0, al0, ah1, al1, ah2, al2, ah3, al3;
            split2(x0a.x, x0a.y, ah0, al0);
            split2(x1a.x, x1a.y, ah1, al1);
            split2(x0b.x, x0b.y, ah2, al2);
            split2(x1b.x, x1b.y, ah3, al3);
            const int k2b = c * 8 + cq;
#pragma unroll
            for (int j = 0; j < 16; ++j) {
                const int col = j * 8 + g;
                uint32_t bh0 = sWhi[col * WSTRIDE + k2b];
                uint32_t bh1 = sWhi[col * WSTRIDE + k2b + 4];
                uint32_t bl0 = sWlo[col * WSTRIDE + k2b];
                uint32_t bl1 = sWlo[col * WSTRIDE + k2b + 4];
                mma16816(acc[j], ah0, ah1, ah2, ah3, bh0, bh1);
                mma16816(acc[j], ah0, ah1, ah2, ah3, bl0, bl1);
                mma16816(acc[j], al0, al1, al2, al3, bh0, bh1);
            }
        }
    }

    // bias + relu
#pragma unroll
    for (int j = 0; j < 16; ++j) {
        const int n0 = j * 8 + cq * 2;
        acc[j][0] = fmaxf(acc[j][0] + sBc[n0],     0.f);
        acc[j][1] = fmaxf(acc[j][1] + sBc[n0 + 1], 0.f);
        acc[j][2] = fmaxf(acc[j][2] + sBc[n0],     0.f);
        acc[j][3] = fmaxf(acc[j][3] + sBc[n0 + 1], 0.f);
    }

    // ---- Stage 2: h @ w_ff^T  (A-fragments straight from acc registers) ----
    __syncthreads();
    for (int i = tid; i < 2048; i += 256) {
        int n = i >> 4, cc = (i & 15) << 2;
        *reinterpret_cast<uint4*>(&sWhi[n * WSTRIDE + cc]) =
            *reinterpret_cast<const uint4*>(&g_Whi[n * 256 + 192 + cc]);
        *reinterpret_cast<uint4*>(&sWlo[n * WSTRIDE + cc]) =
            *reinterpret_cast<const uint4*>(&g_Wlo[n * 256 + 192 + cc]);
    }
    __syncthreads();

    float acc2[16][4];
#pragma unroll
    for (int j = 0; j < 16; ++j) { acc2[j][0]=0.f; acc2[j][1]=0.f; acc2[j][2]=0.f; acc2[j][3]=0.f; }

#pragma unroll
    for (int c = 0; c < 8; ++c) {
        uint32_t ah0, al0, ah1, al1, ah2, al2, ah3, al3;
        split2(acc[2*c][0],   acc[2*c][1],   ah0, al0);
        split2(acc[2*c][2],   acc[2*c][3],   ah1, al1);
        split2(acc[2*c+1][0], acc[2*c+1][1], ah2, al2);
        split2(acc[2*c+1][2], acc[2*c+1][3], ah3, al3);
        const int k2b = c * 8 + cq;
#pragma unroll
        for (int j = 0; j < 16; ++j) {
            const int col = j * 8 + g;
            uint32_t bh0 = sWhi[col * WSTRIDE + k2b];
            uint32_t bh1 = sWhi[col * WSTRIDE + k2b + 4];
            uint32_t bl0 = sWlo[col * WSTRIDE + k2b];
            uint32_t bl1 = sWlo[col * WSTRIDE + k2b + 4];
            mma16816(acc2[j], ah0, ah1, ah2, ah3, bh0, bh1);
            mma16816(acc2[j], ah0, ah1, ah2, ah3, bl0, bl1);
            mma16816(acc2[j], al0, al1, al2, al3, bh0, bh1);
        }
    }

    // ---- epilogue: bias + residual + store 'added' + LN partials ----
    const float* c0 = emb_b + (size_t)(1 + t0c) * D_;
    const float* c1 = emb_b + (size_t)(1 + t1c) * D_;
    float* out_b = out + ((size_t)b * NP1 + 1) * D_;

#pragma unroll
    for (int j = 0; j < 16; ++j) {
        const int f = j * 8 + cq * 2;
        float2 cu0 = *reinterpret_cast<const float2*>(c0 + f);
        float2 cu1 = *reinterpret_cast<const float2*>(c1 + f);
        float add0 = cu0.x + acc2[j][0] + sBf[f];
        float add1 = cu0.y + acc2[j][1] + sBf[f + 1];
        float add2 = cu1.x + acc2[j][2] + sBf[f];
        float add3 = cu1.y + acc2[j][3] + sBf[f + 1];
        if (v0) { float2 o = make_float2(add0, add1);
                  *reinterpret_cast<float2*>(out_b + (size_t)t0 * D_ + f) = o; }
        else { add0 = 0.f; add1 = 0.f; }
        if (v1) { float2 o = make_float2(add2, add3);
                  *reinterpret_cast<float2*>(out_b + (size_t)t1 * D_ + f) = o; }
        else { add2 = 0.f; add3 = 0.f; }

        float s0 = add0 + add2, s1 = add1 + add3;
        float q0 = add0 * add0 + add2 * add2, q1 = add1 * add1 + add3 * add3;
#pragma unroll
        for (int o = 4; o < 32; o <<= 1) {
            s0 += __shfl_xor_sync(0xffffffffu, s0, o);
            s1 += __shfl_xor_sync(0xffffffffu, s1, o);
            q0 += __shfl_xor_sync(0xffffffffu, q0, o);
            q1 += __shfl_xor_sync(0xffffffffu, q1, o);
        }
        if (lane < 4) {
            sS[w * 128 + f] = s0; sS[w * 128 + f + 1] = s1;
            sQ[w * 128 + f] = q0; sQ[w * 128 + f + 1] = q1;
        }
    }
    __syncthreads();
    if (tid < 128) {
        float S = 0.f, Q = 0.f;
#pragma unroll
        for (int ww = 0; ww < 8; ++ww) { S += sS[ww * 128 + tid]; Q += sQ[ww * 128 + tid]; }
        const size_t slot = ((size_t)b * TILES + blockIdx.x) * D_ + tid;
        g_partS[slot] = S;
        g_partQ[slot] = Q;
    }
}

// --------------------------- LN stats + normalize ----------------------------
__global__ void stats_kernel() {
    int b = blockIdx.x, f = threadIdx.x;
    float S = 0.f, Q = 0.f;
    for (int c = 0; c < TILES; ++c) {
        S += g_partS[((size_t)b * TILES + c) * D_ + f];
        Q += g_partQ[((size_t)b * TILES + c) * D_ + f];
    }
    float mean = S * (1.0f / N_);
    float var  = Q * (1.0f / N_) - mean * mean;
    g_mean[b * D_ + f] = mean;
    g_rstd[b * D_ + f] = rsqrtf(var + 1e-5f);
}

__global__ void norm_kernel(const float* __restrict__ emb,
                            const float* __restrict__ norm_w,
                            const float* __restrict__ norm_b,
                            float* __restrict__ out) {
    int t = blockIdx.x;        // 0..5000
    int b = blockIdx.y;        // 0..63
    int f = threadIdx.x;       // 0..127
    size_t idx = ((size_t)b * NP1 + t) * D_ + f;
    if (t == 0) {
        out[idx] = emb[(size_t)b * NP1 * D_ + f];
    } else {
        float x = out[idx];
        out[idx] = (x - g_mean[b * D_ + f]) * g_rstd[b * D_ + f] * norm_w[f] + norm_b[f];
    }
}

// ------------------------------- launcher ------------------------------------
extern "C" void kernel_launch(void* const* d_in, const int* in_sizes, int n_in,
                              void* d_out, int out_size) {
    // locate solution_neighbours (the only input with B*N*2 elements)
    int i0 = 0;
    for (int i = 0; i < n_in; ++i) if (in_sizes[i] == B_ * N_ * 2) { i0 = i; break; }
    const int*   sn      = (const int*)d_in[i0];
    const float* emb     = (const float*)d_in[i0 + 1];
    const float* w_left  = (const float*)d_in[i0 + 2];
    const float* w_right = (const float*)d_in[i0 + 3];
    const float* w_comb  = (const float*)d_in[i0 + 4];
    const float* b_comb  = (const float*)d_in[i0 + 5];
    const float* w_ff    = (const float*)d_in[i0 + 6];
    const float* b_ff    = (const float*)d_in[i0 + 7];
    const float* norm_w  = (const float*)d_in[i0 + 8];
    const float* norm_b  = (const float*)d_in[i0 + 9];
    float* out = (float*)d_out;

    cudaFuncSetAttribute(main_kernel, cudaFuncAttributeMaxDynamicSharedMemorySize, SMEM_BYTES);

    prep1_kernel<<<128, 128>>>(w_comb, w_left, w_right, w_ff);
    prep2_kernel<<<128, 256>>>();
    main_kernel<<<dim3(TILES, B_), 256, SMEM_BYTES>>>(sn, emb, b_comb, b_ff, out);
    stats_kernel<<<B_, 128>>>();
    norm_kernel<<<dim3(NP1, B_), 128>>>(emb, norm_w, norm_b, out);
}

// round 4
// speedup vs baseline: 1.3687x; 1.3687x over previous
#include <cuda_runtime.h>
#include <cuda_bf16.h>
#include <cstdint>

#define B_   64
#define N_   5000
#define NP1  5001
#define D_   128
#define TILES 40
#define SP   68     // smem weight row stride in 64-bit pairs: >=64, ==4 mod 16 -> conflict-free LDS.64

// ------------------------- device scratch (no allocs) -----------------------
__device__ float    g_W1f[128 * 512];          // fused fp32 weights [n][512]
__device__ uint32_t g_Wp[128 * 256 * 2];       // packed bf16 {hi,lo} pairs [n][k2][2]
__device__ float    g_partS[B_ * TILES * D_];
__device__ float    g_partQ[B_ * TILES * D_];
__device__ float    g_mean[B_ * D_];
__device__ float    g_rstd[B_ * D_];

// ------------------------------- helpers ------------------------------------
__device__ __forceinline__ void split2(float x, float y, uint32_t& hi, uint32_t& lo) {
    __nv_bfloat162 h = __floats2bfloat162_rn(x, y);
    float lx = x - __bfloat162float(h.x);
    float ly = y - __bfloat162float(h.y);
    __nv_bfloat162 l = __floats2bfloat162_rn(lx, ly);
    hi = *reinterpret_cast<uint32_t*>(&h);
    lo = *reinterpret_cast<uint32_t*>(&l);
}

__device__ __forceinline__ void mma16816(float (&c)[4],
                                         uint32_t a0, uint32_t a1, uint32_t a2, uint32_t a3,
                                         uint32_t b0, uint32_t b1) {
    asm("mma.sync.aligned.m16n8k16.row.col.f32.bf16.bf16.f32 "
        "{%0,%1,%2,%3}, {%4,%5,%6,%7}, {%8,%9}, {%0,%1,%2,%3};"
        : "+f"(c[0]), "+f"(c[1]), "+f"(c[2]), "+f"(c[3])
        : "r"(a0), "r"(a1), "r"(a2), "r"(a3), "r"(b0), "r"(b1));
}

__device__ __forceinline__ void cp16(uint32_t* dst_smem, const uint32_t* src) {
    unsigned sa = (unsigned)__cvta_generic_to_shared(dst_smem);
    asm volatile("cp.async.cg.shared.global [%0], [%1], 16;\n" :: "r"(sa), "l"(src));
}
__device__ __forceinline__ void cp_commit() { asm volatile("cp.async.commit_group;\n"); }
template <int N>
__device__ __forceinline__ void cp_wait() { asm volatile("cp.async.wait_group %0;\n" :: "n"(N)); }

// -------------------------- weight prep kernels ------------------------------
__global__ void prep1_kernel(const float* __restrict__ w_comb,
                             const float* __restrict__ w_left,
                             const float* __restrict__ w_right,
                             const float* __restrict__ w_ff) {
    int n = blockIdx.x, k = threadIdx.x;          // 128 x 128
    float* row = g_W1f + n * 512;
    row[k] = w_comb[n * 256 + k];
    float a1 = 0.f, a2 = 0.f;
    for (int m = 0; m < 128; ++m) {
        float wc = w_comb[n * 256 + 128 + m];
        a1 = fmaf(wc, w_left[m * 128 + k], a1);
        a2 = fmaf(wc, w_right[m * 128 + k], a2);
    }
    row[128 + k] = a1;
    row[256 + k] = a2;
    row[384 + k] = w_ff[n * 128 + k];
}

__global__ void prep2_kernel() {
    int n = blockIdx.x, k2 = threadIdx.x;         // 128 x 256
    float2 x = *reinterpret_cast<const float2*>(g_W1f + n * 512 + 2 * k2);
    uint32_t hi, lo;
    split2(x.x, x.y, hi, lo);
    g_Wp[n * 512 + k2 * 2]     = hi;
    g_Wp[n * 512 + k2 * 2 + 1] = lo;
}

// --------------------------- main fused kernel -------------------------------
// smem (words): sW[2][128*SP*2] | sBc[128] | sBf[128] | sS[8*128] | sQ[8*128]
#define WBUF_WORDS (128 * SP * 2)
#define SMEM_WORDS (2 * WBUF_WORDS + 256 + 2 * 8 * 128)
#define SMEM_BYTES (SMEM_WORDS * 4)

// stage weight slice s (64 k2-pairs per row) into smem buffer
__device__ __forceinline__ void copy_slice_async(uint32_t* dst, int s, int tid) {
    const uint32_t* src = g_Wp + s * 128;
#pragma unroll
    for (int i = tid; i < 4096; i += 256) {       // 4096 x 16B = 64KB
        int n = i >> 5, k2 = (i & 31) * 2;        // k2 even, 2 pairs per cp16
        cp16(&dst[(n * SP + k2) * 2], src + n * 512 + k2 * 2);
    }
    cp_commit();
}

// one K=128 GEMM slice over gathered rows p0/p1
__device__ __forceinline__ void compute_slice(const uint32_t* __restrict__ sW,
                                              const float* __restrict__ p0,
                                              const float* __restrict__ p1,
                                              int cq, int g, float (&acc)[16][4]) {
    float2 n0a = *reinterpret_cast<const float2*>(p0 + cq * 2);
    float2 n0b = *reinterpret_cast<const float2*>(p0 + cq * 2 + 8);
    float2 n1a = *reinterpret_cast<const float2*>(p1 + cq * 2);
    float2 n1b = *reinterpret_cast<const float2*>(p1 + cq * 2 + 8);
#pragma unroll
    for (int c = 0; c < 8; ++c) {
        float2 x0a = n0a, x0b = n0b, x1a = n1a, x1b = n1b;
        if (c < 7) {
            const int kc = (c + 1) * 16 + cq * 2;
            n0a = *reinterpret_cast<const float2*>(p0 + kc);
            n0b = *reinterpret_cast<const float2*>(p0 + kc + 8);
            n1a = *reinterpret_cast<const float2*>(p1 + kc);
            n1b = *reinterpret_cast<const float2*>(p1 + kc + 8);
        }
        uint32_t ah0, al0, ah1, al1, ah2, al2, ah3, al3;
        split2(x0a.x, x0a.y, ah0, al0);
        split2(x1a.x, x1a.y, ah1, al1);
        split2(x0b.x, x0b.y, ah2, al2);
        split2(x1b.x, x1b.y, ah3, al3);
        const int k2b = c * 8 + cq;
#pragma unroll
        for (int j = 0; j < 16; ++j) {
            const int col = j * 8 + g;
            uint2 w0 = *reinterpret_cast<const uint2*>(&sW[(col * SP + k2b) * 2]);
            uint2 w1 = *reinterpret_cast<const uint2*>(&sW[(col * SP + k2b + 4) * 2]);
            mma16816(acc[j], ah0, ah1, ah2, ah3, w0.x, w1.x);
            mma16816(acc[j], ah0, ah1, ah2, ah3, w0.y, w1.y);
            mma16816(acc[j], al0, al1, al2, al3, w0.x, w1.x);
        }
    }
}

__global__ void __launch_bounds__(256, 1)
main_kernel(const int* __restrict__ sn, const float* __restrict__ emb,
            const float* __restrict__ b_comb, const float* __restrict__ b_ff,
            float* __restrict__ out) {
    extern __shared__ uint32_t smem[];
    uint32_t* sW0 = smem;
    uint32_t* sW1 = smem + WBUF_WORDS;
    float* sBc = reinterpret_cast<float*>(smem + 2 * WBUF_WORDS);
    float* sBf = sBc + 128;
    float* sS  = sBf + 128;
    float* sQ  = sS + 8 * 128;

    const int tid  = threadIdx.x;
    const int w    = tid >> 5;
    const int lane = tid & 31;
    const int g    = lane >> 2;
    const int cq   = lane & 3;
    const int b    = blockIdx.y;

    const int tokBase = blockIdx.x * 128 + w * 16;
    const int t0 = tokBase + g;
    const int t1 = t0 + 8;
    const bool v0 = (t0 < N_), v1 = (t1 < N_);
    const int t0c = v0 ? t0 : (N_ - 1);
    const int t1c = v1 ? t1 : (N_ - 1);

    const float* emb_b = emb + (size_t)b * NP1 * D_;
    const int*   sn_b  = sn  + (size_t)b * N_ * 2;

    // kick off weight staging for slices 0 and 1 immediately
    copy_slice_async(sW0, 0, tid);
    copy_slice_async(sW1, 1, tid);

    // hoisted gather indices
    const int li0 = sn_b[t0c * 2],     li1 = sn_b[t1c * 2];
    const int ri0 = sn_b[t0c * 2 + 1], ri1 = sn_b[t1c * 2 + 1];
    const float* c0p = emb_b + (size_t)(1 + t0c) * D_;
    const float* c1p = emb_b + (size_t)(1 + t1c) * D_;

    if (tid < 128) sBc[tid] = b_comb[tid];
    else           sBf[tid - 128] = b_ff[tid - 128];

    float acc[16][4];
#pragma unroll
    for (int j = 0; j < 16; ++j) { acc[j][0]=0.f; acc[j][1]=0.f; acc[j][2]=0.f; acc[j][3]=0.f; }

    // ---- Stage 1: [cust | left | right] @ W1^T ----
    cp_wait<1>(); __syncthreads();                       // buf0 ready
    compute_slice(sW0, c0p, c1p, cq, g, acc);

    cp_wait<0>(); __syncthreads();                       // buf1 ready, buf0 free
    copy_slice_async(sW0, 2, tid);
    compute_slice(sW1, emb_b + (size_t)li0 * D_, emb_b + (size_t)li1 * D_, cq, g, acc);

    cp_wait<0>(); __syncthreads();                       // buf0(slice2) ready, buf1 free
    copy_slice_async(sW1, 3, tid);                       // w_ff
    compute_slice(sW0, emb_b + (size_t)ri0 * D_, emb_b + (size_t)ri1 * D_, cq, g, acc);

    // bias + relu
#pragma unroll
    for (int j = 0; j < 16; ++j) {
        const int n0 = j * 8 + cq * 2;
        acc[j][0] = fmaxf(acc[j][0] + sBc[n0],     0.f);
        acc[j][1] = fmaxf(acc[j][1] + sBc[n0 + 1], 0.f);
        acc[j][2] = fmaxf(acc[j][2] + sBc[n0],     0.f);
        acc[j][3] = fmaxf(acc[j][3] + sBc[n0 + 1], 0.f);
    }

    // ---- Stage 2: h @ w_ff^T (A-fragments straight from acc) ----
    cp_wait<0>(); __syncthreads();

    float acc2[16][4];
#pragma unroll
    for (int j = 0; j < 16; ++j) { acc2[j][0]=0.f; acc2[j][1]=0.f; acc2[j][2]=0.f; acc2[j][3]=0.f; }

#pragma unroll
    for (int c = 0; c < 8; ++c) {
        uint32_t ah0, al0, ah1, al1, ah2, al2, ah3, al3;
        split2(acc[2*c][0],   acc[2*c][1],   ah0, al0);
        split2(acc[2*c][2],   acc[2*c][3],   ah1, al1);
        split2(acc[2*c+1][0], acc[2*c+1][1], ah2, al2);
        split2(acc[2*c+1][2], acc[2*c+1][3], ah3, al3);
        const int k2b = c * 8 + cq;
#pragma unroll
        for (int j = 0; j < 16; ++j) {
            const int col = j * 8 + g;
            uint2 w0 = *reinterpret_cast<const uint2*>(&sW1[(col * SP + k2b) * 2]);
            uint2 w1 = *reinterpret_cast<const uint2*>(&sW1[(col * SP + k2b + 4) * 2]);
            mma16816(acc2[j], ah0, ah1, ah2, ah3, w0.x, w1.x);
            mma16816(acc2[j], ah0, ah1, ah2, ah3, w0.y, w1.y);
            mma16816(acc2[j], al0, al1, al2, al3, w0.x, w1.x);
        }
    }

    // ---- epilogue: bias + residual + store 'added' + LN partials ----
    float* out_b = out + ((size_t)b * NP1 + 1) * D_;

#pragma unroll
    for (int j = 0; j < 16; ++j) {
        const int f = j * 8 + cq * 2;
        float2 cu0 = *reinterpret_cast<const float2*>(c0p + f);
        float2 cu1 = *reinterpret_cast<const float2*>(c1p + f);
        float add0 = cu0.x + acc2[j][0] + sBf[f];
        float add1 = cu0.y + acc2[j][1] + sBf[f + 1];
        float add2 = cu1.x + acc2[j][2] + sBf[f];
        float add3 = cu1.y + acc2[j][3] + sBf[f + 1];
        if (v0) { *reinterpret_cast<float2*>(out_b + (size_t)t0 * D_ + f) = make_float2(add0, add1); }
        else { add0 = 0.f; add1 = 0.f; }
        if (v1) { *reinterpret_cast<float2*>(out_b + (size_t)t1 * D_ + f) = make_float2(add2, add3); }
        else { add2 = 0.f; add3 = 0.f; }

        float s0 = add0 + add2, s1 = add1 + add3;
        float q0 = add0 * add0 + add2 * add2, q1 = add1 * add1 + add3 * add3;
#pragma unroll
        for (int o = 4; o < 32; o <<= 1) {
            s0 += __shfl_xor_sync(0xffffffffu, s0, o);
            s1 += __shfl_xor_sync(0xffffffffu, s1, o);
            q0 += __shfl_xor_sync(0xffffffffu, q0, o);
            q1 += __shfl_xor_sync(0xffffffffu, q1, o);
        }
        if (lane < 4) {
            sS[w * 128 + f] = s0; sS[w * 128 + f + 1] = s1;
            sQ[w * 128 + f] = q0; sQ[w * 128 + f + 1] = q1;
        }
    }
    __syncthreads();
    if (tid < 128) {
        float S = 0.f, Q = 0.f;
#pragma unroll
        for (int ww = 0; ww < 8; ++ww) { S += sS[ww * 128 + tid]; Q += sQ[ww * 128 + tid]; }
        const size_t slot = ((size_t)b * TILES + blockIdx.x) * D_ + tid;
        g_partS[slot] = S;
        g_partQ[slot] = Q;
    }
}

// --------------------------- LN stats + normalize ----------------------------
__global__ void stats_kernel() {
    int b = blockIdx.x, f = threadIdx.x;
    float S = 0.f, Q = 0.f;
    for (int c = 0; c < TILES; ++c) {
        S += g_partS[((size_t)b * TILES + c) * D_ + f];
        Q += g_partQ[((size_t)b * TILES + c) * D_ + f];
    }
    float mean = S * (1.0f / N_);
    float var  = Q * (1.0f / N_) - mean * mean;
    g_mean[b * D_ + f] = mean;
    g_rstd[b * D_ + f] = rsqrtf(var + 1e-5f);
}

__global__ void __launch_bounds__(256)
norm_kernel(const float* __restrict__ norm_w, const float* __restrict__ norm_b,
            float* __restrict__ out) {
    int v = blockIdx.x * 256 + threadIdx.x;        // float4 index over 64*5000*32
    int b = v / (N_ * 32);
    int r = v - b * (N_ * 32);
    int t = r >> 5;
    int f4 = (r & 31) * 4;
    size_t idx = ((size_t)b * NP1 + 1 + t) * D_ + f4;
    float4 x  = *reinterpret_cast<float4*>(out + idx);
    float4 m  = *reinterpret_cast<const float4*>(g_mean + b * D_ + f4);
    float4 s  = *reinterpret_cast<const float4*>(g_rstd + b * D_ + f4);
    float4 ww = *reinterpret_cast<const float4*>(norm_w + f4);
    float4 bb = *reinterpret_cast<const float4*>(norm_b + f4);
    x.x = (x.x - m.x) * s.x * ww.x + bb.x;
    x.y = (x.y - m.y) * s.y * ww.y + bb.y;
    x.z = (x.z - m.z) * s.z * ww.z + bb.z;
    x.w = (x.w - m.w) * s.w * ww.w + bb.w;
    *reinterpret_cast<float4*>(out + idx) = x;
}

// ------------------------------- launcher ------------------------------------
extern "C" void kernel_launch(void* const* d_in, const int* in_sizes, int n_in,
                              void* d_out, int out_size) {
    int i0 = 0;
    for (int i = 0; i < n_in; ++i) if (in_sizes[i] == B_ * N_ * 2) { i0 = i; break; }
    const int*   sn      = (const int*)d_in[i0];
    const float* emb     = (const float*)d_in[i0 + 1];
    const float* w_left  = (const float*)d_in[i0 + 2];
    const float* w_right = (const float*)d_in[i0 + 3];
    const float* w_comb  = (const float*)d_in[i0 + 4];
    const float* b_comb  = (const float*)d_in[i0 + 5];
    const float* w_ff    = (const float*)d_in[i0 + 6];
    const float* b_ff    = (const float*)d_in[i0 + 7];
    const float* norm_w  = (const float*)d_in[i0 + 8];
    const float* norm_b  = (const float*)d_in[i0 + 9];
    float* out = (float*)d_out;

    cudaFuncSetAttribute(main_kernel, cudaFuncAttributeMaxDynamicSharedMemorySize, SMEM_BYTES);

    // depot row (token 0) passthrough: 64 rows of 512B, pitch NP1*512B
    cudaMemcpy2DAsync(out, (size_t)NP1 * D_ * sizeof(float),
                      emb, (size_t)NP1 * D_ * sizeof(float),
                      D_ * sizeof(float), B_, cudaMemcpyDeviceToDevice);

    prep1_kernel<<<128, 128>>>(w_comb, w_left, w_right, w_ff);
    prep2_kernel<<<128, 256>>>();
    main_kernel<<<dim3(TILES, B_), 256, SMEM_BYTES>>>(sn, emb, b_comb, b_ff, out);
    stats_kernel<<<B_, 128>>>();
    norm_kernel<<<B_ * N_ * 32 / 256, 256>>>(norm_w, norm_b, out);
}

// round 5
// speedup vs baseline: 1.4271x; 1.0427x over previous
#include <cuda_runtime.h>
#include <cuda_bf16.h>
#include <cstdint>

#define B_   64
#define N_   5000
#define NP1  5001
#define D_   128
#define TILES 40
#define SP   36     // smem weight row stride in 64-bit pairs (>=32, ==4 mod 16 -> conflict-free LDS.64)

// ------------------------- device scratch (no allocs) -----------------------
__device__ uint32_t g_Wp[128 * 256 * 2];       // packed bf16 {hi,lo} pairs [n][k2][2]
__device__ float    g_partS[B_ * TILES * D_];
__device__ float    g_partQ[B_ * TILES * D_];
__device__ float    g_mean[B_ * D_];
__device__ float    g_rstd[B_ * D_];

// ------------------------------- helpers ------------------------------------
__device__ __forceinline__ void split2(float x, float y, uint32_t& hi, uint32_t& lo) {
    __nv_bfloat162 h = __floats2bfloat162_rn(x, y);
    float lx = x - __bfloat162float(h.x);
    float ly = y - __bfloat162float(h.y);
    __nv_bfloat162 l = __floats2bfloat162_rn(lx, ly);
    hi = *reinterpret_cast<uint32_t*>(&h);
    lo = *reinterpret_cast<uint32_t*>(&l);
}

__device__ __forceinline__ void mma16816(float (&c)[4],
                                         uint32_t a0, uint32_t a1, uint32_t a2, uint32_t a3,
                                         uint32_t b0, uint32_t b1) {
    asm("mma.sync.aligned.m16n8k16.row.col.f32.bf16.bf16.f32 "
        "{%0,%1,%2,%3}, {%4,%5,%6,%7}, {%8,%9}, {%0,%1,%2,%3};"
        : "+f"(c[0]), "+f"(c[1]), "+f"(c[2]), "+f"(c[3])
        : "r"(a0), "r"(a1), "r"(a2), "r"(a3), "r"(b0), "r"(b1));
}

__device__ __forceinline__ void cp16(uint32_t* dst_smem, const uint32_t* src) {
    unsigned sa = (unsigned)__cvta_generic_to_shared(dst_smem);
    asm volatile("cp.async.cg.shared.global [%0], [%1], 16;\n" :: "r"(sa), "l"(src));
}
__device__ __forceinline__ void cp_commit() { asm volatile("cp.async.commit_group;\n"); }
template <int N>
__device__ __forceinline__ void cp_wait() { asm volatile("cp.async.wait_group %0;\n" :: "n"(N)); }

// -------------------------- fused weight prep --------------------------------
// block n: row[512] = [wc1 | wc2@wl | wc2@wr | wff], then bf16 hi/lo pack
__global__ void prep_kernel(const float* __restrict__ w_comb,
                            const float* __restrict__ w_left,
                            const float* __restrict__ w_right,
                            const float* __restrict__ w_ff) {
    __shared__ float row[512];
    int n = blockIdx.x, k = threadIdx.x;          // 128 x 128
    row[k] = w_comb[n * 256 + k];
    float a1 = 0.f, a2 = 0.f;
    for (int m = 0; m < 128; ++m) {
        float wc = w_comb[n * 256 + 128 + m];
        a1 = fmaf(wc, w_left[m * 128 + k], a1);
        a2 = fmaf(wc, w_right[m * 128 + k], a2);
    }
    row[128 + k] = a1;
    row[256 + k] = a2;
    row[384 + k] = w_ff[n * 128 + k];
    __syncthreads();
#pragma unroll
    for (int r = 0; r < 2; ++r) {
        int k2 = k + r * 128;
        uint32_t hi, lo;
        split2(row[2 * k2], row[2 * k2 + 1], hi, lo);
        g_Wp[n * 512 + k2 * 2]     = hi;
        g_Wp[n * 512 + k2 * 2 + 1] = lo;
    }
}

// --------------------------- main fused kernel -------------------------------
// smem (words): sW[2][128*SP*2] | sBc[128] | sBf[128] | sS[8*128] | sQ[8*128]
#define WBUF_WORDS (128 * SP * 2)
#define SMEM_WORDS (2 * WBUF_WORDS + 256 + 2 * 8 * 128)
#define SMEM_BYTES (SMEM_WORDS * 4)

// stage weight sub-slice s (32 k2-pairs per row, K=64) into smem buffer
__device__ __forceinline__ void copy_slice_async(uint32_t* dst, int s, int tid) {
    const uint32_t* src = g_Wp + s * 64;          // 32 pairs = 64 words offset per sub-slice
#pragma unroll
    for (int i = tid; i < 2048; i += 256) {       // 2048 x 16B = 32KB
        int n = i >> 4, k2 = (i & 15) * 2;        // k2 even, 2 pairs per cp16
        cp16(&dst[(n * SP + k2) * 2], src + n * 512 + k2 * 2);
    }
    cp_commit();
}

// one K=64 GEMM sub-slice over gathered rows p0/p1 (pre-offset by koff)
__device__ __forceinline__ void compute_slice(const uint32_t* __restrict__ sW,
                                              const float* __restrict__ p0,
                                              const float* __restrict__ p1,
                                              int cq, int g, float (&acc)[16][4]) {
    float2 n0a = *reinterpret_cast<const float2*>(p0 + cq * 2);
    float2 n0b = *reinterpret_cast<const float2*>(p0 + cq * 2 + 8);
    float2 n1a = *reinterpret_cast<const float2*>(p1 + cq * 2);
    float2 n1b = *reinterpret_cast<const float2*>(p1 + cq * 2 + 8);
#pragma unroll
    for (int c = 0; c < 4; ++c) {
        float2 x0a = n0a, x0b = n0b, x1a = n1a, x1b = n1b;
        if (c < 3) {
            const int kc = (c + 1) * 16 + cq * 2;
            n0a = *reinterpret_cast<const float2*>(p0 + kc);
            n0b = *reinterpret_cast<const float2*>(p0 + kc + 8);
            n1a = *reinterpret_cast<const float2*>(p1 + kc);
            n1b = *reinterpret_cast<const float2*>(p1 + kc + 8);
        }
        uint32_t ah0, al0, ah1, al1, ah2, al2, ah3, al3;
        split2(x0a.x, x0a.y, ah0, al0);
        split2(x1a.x, x1a.y, ah1, al1);
        split2(x0b.x, x0b.y, ah2, al2);
        split2(x1b.x, x1b.y, ah3, al3);
        const int k2b = c * 8 + cq;
#pragma unroll
        for (int j = 0; j < 16; ++j) {
            const int col = j * 8 + g;
            uint2 w0 = *reinterpret_cast<const uint2*>(&sW[(col * SP + k2b) * 2]);
            uint2 w1 = *reinterpret_cast<const uint2*>(&sW[(col * SP + k2b + 4) * 2]);
            mma16816(acc[j], ah0, ah1, ah2, ah3, w0.x, w1.x);
            mma16816(acc[j], ah0, ah1, ah2, ah3, w0.y, w1.y);
            mma16816(acc[j], al0, al1, al2, al3, w0.x, w1.x);
        }
    }
}

__global__ void __launch_bounds__(256, 2)
main_kernel(const int* __restrict__ sn, const float* __restrict__ emb,
            const float* __restrict__ b_comb, const float* __restrict__ b_ff,
            float* __restrict__ out) {
    extern __shared__ uint32_t smem[];
    uint32_t* sW0 = smem;
    uint32_t* sW1 = smem + WBUF_WORDS;
    float* sBc = reinterpret_cast<float*>(smem + 2 * WBUF_WORDS);
    float* sBf = sBc + 128;
    float* sS  = sBf + 128;
    float* sQ  = sS + 8 * 128;

    const int tid  = threadIdx.x;
    const int w    = tid >> 5;
    const int lane = tid & 31;
    const int g    = lane >> 2;
    const int cq   = lane & 3;
    const int b    = blockIdx.y;

    const int tokBase = blockIdx.x * 128 + w * 16;
    const int t0 = tokBase + g;
    const int t1 = t0 + 8;
    const bool v0 = (t0 < N_), v1 = (t1 < N_);
    const int t0c = v0 ? t0 : (N_ - 1);
    const int t1c = v1 ? t1 : (N_ - 1);

    const float* emb_b = emb + (size_t)b * NP1 * D_;
    const int*   sn_b  = sn  + (size_t)b * N_ * 2;

    copy_slice_async(sW0, 0, tid);
    copy_slice_async(sW1, 1, tid);

    const int li0 = sn_b[t0c * 2],     li1 = sn_b[t1c * 2];
    const int ri0 = sn_b[t0c * 2 + 1], ri1 = sn_b[t1c * 2 + 1];
    const float* c0p = emb_b + (size_t)(1 + t0c) * D_;
    const float* c1p = emb_b + (size_t)(1 + t1c) * D_;
    const float* l0p = emb_b + (size_t)li0 * D_;
    const float* l1p = emb_b + (size_t)li1 * D_;
    const float* r0p = emb_b + (size_t)ri0 * D_;
    const float* r1p = emb_b + (size_t)ri1 * D_;

    if (tid < 128) sBc[tid] = b_comb[tid];
    else           sBf[tid - 128] = b_ff[tid - 128];

    float acc[16][4];
#pragma unroll
    for (int j = 0; j < 16; ++j) { acc[j][0]=0.f; acc[j][1]=0.f; acc[j][2]=0.f; acc[j][3]=0.f; }

    // ---- Stage 1: 6 K=64 sub-slices, double buffered ----
    cp_wait<1>(); __syncthreads();                        // b0(s0) ready
    compute_slice(sW0, c0p, c1p, cq, g, acc);
    cp_wait<0>(); __syncthreads();                        // b1(s1) ready, b0 free
    copy_slice_async(sW0, 2, tid);
    compute_slice(sW1, c0p + 64, c1p + 64, cq, g, acc);
    cp_wait<0>(); __syncthreads();
    copy_slice_async(sW1, 3, tid);
    compute_slice(sW0, l0p, l1p, cq, g, acc);
    cp_wait<0>(); __syncthreads();
    copy_slice_async(sW0, 4, tid);
    compute_slice(sW1, l0p + 64, l1p + 64, cq, g, acc);
    cp_wait<0>(); __syncthreads();
    copy_slice_async(sW1, 5, tid);
    compute_slice(sW0, r0p, r1p, cq, g, acc);
    cp_wait<0>(); __syncthreads();
    copy_slice_async(sW0, 6, tid);
    compute_slice(sW1, r0p + 64, r1p + 64, cq, g, acc);
    cp_wait<0>(); __syncthreads();                        // b0(s6) ready, b1 free
    copy_slice_async(sW1, 7, tid);

    // bias + relu (overlaps s7 staging)
#pragma unroll
    for (int j = 0; j < 16; ++j) {
        const int n0 = j * 8 + cq * 2;
        acc[j][0] = fmaxf(acc[j][0] + sBc[n0],     0.f);
        acc[j][1] = fmaxf(acc[j][1] + sBc[n0 + 1], 0.f);
        acc[j][2] = fmaxf(acc[j][2] + sBc[n0],     0.f);
        acc[j][3] = fmaxf(acc[j][3] + sBc[n0 + 1], 0.f);
    }
    cp_wait<0>(); __syncthreads();                        // b1(s7) ready

    // ---- Stage 2 + fused epilogue, j-blocks of 4 (register cap) ----
    float* out_b = out + ((size_t)b * NP1 + 1) * D_;

#pragma unroll
    for (int jb = 0; jb < 4; ++jb) {
        float a2[4][4];
#pragma unroll
        for (int jj = 0; jj < 4; ++jj) { a2[jj][0]=0.f; a2[jj][1]=0.f; a2[jj][2]=0.f; a2[jj][3]=0.f; }
#pragma unroll
        for (int c = 0; c < 8; ++c) {
            const uint32_t* sWc = (c < 4) ? sW0 : sW1;
            uint32_t ah0, al0, ah1, al1, ah2, al2, ah3, al3;
            split2(acc[2*c][0],   acc[2*c][1],   ah0, al0);
            split2(acc[2*c][2],   acc[2*c][3],   ah1, al1);
            split2(acc[2*c+1][0], acc[2*c+1][1], ah2, al2);
            split2(acc[2*c+1][2], acc[2*c+1][3], ah3, al3);
            const int k2b = (c & 3) * 8 + cq;
#pragma unroll
            for (int jj = 0; jj < 4; ++jj) {
                const int col = (jb * 4 + jj) * 8 + g;
                uint2 w0 = *reinterpret_cast<const uint2*>(&sWc[(col * SP + k2b) * 2]);
                uint2 w1 = *reinterpret_cast<const uint2*>(&sWc[(col * SP + k2b + 4) * 2]);
                mma16816(a2[jj], ah0, ah1, ah2, ah3, w0.x, w1.x);
                mma16816(a2[jj], ah0, ah1, ah2, ah3, w0.y, w1.y);
                mma16816(a2[jj], al0, al1, al2, al3, w0.x, w1.x);
            }
        }
        // epilogue for these 4 j's
#pragma unroll
        for (int jj = 0; jj < 4; ++jj) {
            const int f = (jb * 4 + jj) * 8 + cq * 2;
            float2 cu0 = *reinterpret_cast<const float2*>(c0p + f);
            float2 cu1 = *reinterpret_cast<const float2*>(c1p + f);
            float add0 = cu0.x + a2[jj][0] + sBf[f];
            float add1 = cu0.y + a2[jj][1] + sBf[f + 1];
            float add2 = cu1.x + a2[jj][2] + sBf[f];
            float add3 = cu1.y + a2[jj][3] + sBf[f + 1];
            if (v0) { *reinterpret_cast<float2*>(out_b + (size_t)t0 * D_ + f) = make_float2(add0, add1); }
            else { add0 = 0.f; add1 = 0.f; }
            if (v1) { *reinterpret_cast<float2*>(out_b + (size_t)t1 * D_ + f) = make_float2(add2, add3); }
            else { add2 = 0.f; add3 = 0.f; }

            float s0 = add0 + add2, s1 = add1 + add3;
            float q0 = add0 * add0 + add2 * add2, q1 = add1 * add1 + add3 * add3;
#pragma unroll
            for (int o = 4; o < 32; o <<= 1) {
                s0 += __shfl_xor_sync(0xffffffffu, s0, o);
                s1 += __shfl_xor_sync(0xffffffffu, s1, o);
                q0 += __shfl_xor_sync(0xffffffffu, q0, o);
                q1 += __shfl_xor_sync(0xffffffffu, q1, o);
            }
            if (lane < 4) {
                sS[w * 128 + f] = s0; sS[w * 128 + f + 1] = s1;
                sQ[w * 128 + f] = q0; sQ[w * 128 + f + 1] = q1;
            }
        }
    }
    __syncthreads();
    if (tid < 128) {
        float S = 0.f, Q = 0.f;
#pragma unroll
        for (int ww = 0; ww < 8; ++ww) { S += sS[ww * 128 + tid]; Q += sQ[ww * 128 + tid]; }
        const size_t slot = ((size_t)b * TILES + blockIdx.x) * D_ + tid;
        g_partS[slot] = S;
        g_partQ[slot] = Q;
    }
}

// --------------------------- LN stats + normalize ----------------------------
__global__ void stats_kernel() {
    int b = blockIdx.x, f = threadIdx.x;
    float S = 0.f, Q = 0.f;
    for (int c = 0; c < TILES; ++c) {
        S += g_partS[((size_t)b * TILES + c) * D_ + f];
        Q += g_partQ[((size_t)b * TILES + c) * D_ + f];
    }
    float mean = S * (1.0f / N_);
    float var  = Q * (1.0f / N_) - mean * mean;
    g_mean[b * D_ + f] = mean;
    g_rstd[b * D_ + f] = rsqrtf(var + 1e-5f);
}

__global__ void __launch_bounds__(256)
norm_kernel(const float* __restrict__ norm_w, const float* __restrict__ norm_b,
            float* __restrict__ out) {
    int v = blockIdx.x * 256 + threadIdx.x;        // float4 index over 64*5000*32
    int b = v / (N_ * 32);
    int r = v - b * (N_ * 32);
    int t = r >> 5;
    int f4 = (r & 31) * 4;
    size_t idx = ((size_t)b * NP1 + 1 + t) * D_ + f4;
    float4 x  = *reinterpret_cast<float4*>(out + idx);
    float4 m  = *reinterpret_cast<const float4*>(g_mean + b * D_ + f4);
    float4 s  = *reinterpret_cast<const float4*>(g_rstd + b * D_ + f4);
    float4 ww = *reinterpret_cast<const float4*>(norm_w + f4);
    float4 bb = *reinterpret_cast<const float4*>(norm_b + f4);
    x.x = (x.x - m.x) * s.x * ww.x + bb.x;
    x.y = (x.y - m.y) * s.y * ww.y + bb.y;
    x.z = (x.z - m.z) * s.z * ww.z + bb.z;
    x.w = (x.w - m.w) * s.w * ww.w + bb.w;
    *reinterpret_cast<float4*>(out + idx) = x;
}

// ------------------------------- launcher ------------------------------------
extern "C" void kernel_launch(void* const* d_in, const int* in_sizes, int n_in,
                              void* d_out, int out_size) {
    int i0 = 0;
    for (int i = 0; i < n_in; ++i) if (in_sizes[i] == B_ * N_ * 2) { i0 = i; break; }
    const int*   sn      = (const int*)d_in[i0];
    const float* emb     = (const float*)d_in[i0 + 1];
    const float* w_left  = (const float*)d_in[i0 + 2];
    const float* w_right = (const float*)d_in[i0 + 3];
    const float* w_comb  = (const float*)d_in[i0 + 4];
    const float* b_comb  = (const float*)d_in[i0 + 5];
    const float* w_ff    = (const float*)d_in[i0 + 6];
    const float* b_ff    = (const float*)d_in[i0 + 7];
    const float* norm_w  = (const float*)d_in[i0 + 8];
    const float* norm_b  = (const float*)d_in[i0 + 9];
    float* out = (float*)d_out;

    cudaFuncSetAttribute(main_kernel, cudaFuncAttributeMaxDynamicSharedMemorySize, SMEM_BYTES);

    // depot row (token 0) passthrough
    cudaMemcpy2DAsync(out, (size_t)NP1 * D_ * sizeof(float),
                      emb, (size_t)NP1 * D_ * sizeof(float),
                      D_ * sizeof(float), B_, cudaMemcpyDeviceToDevice);

    prep_kernel<<<128, 128>>>(w_comb, w_left, w_right, w_ff);
    main_kernel<<<dim3(TILES, B_), 256, SMEM_BYTES>>>(sn, emb, b_comb, b_ff, out);
    stats_kernel<<<B_, 128>>>();
    norm_kernel<<<B_ * N_ * 32 / 256, 256>>>(norm_w, norm_b, out);
}

// round 7
// speedup vs baseline: 1.9083x; 1.3372x over previous
#include <cuda_runtime.h>
#include <cuda_bf16.h>
#include <cstdint>

#define B_   64
#define N_   5000
#define NP1  5001
#define D_   128
#define TILES 40
#define SPU  20     // smem B row stride in uint2 (==4 mod 16 -> conflict-free LDS.64)

// ------------------------- device scratch (no allocs) -----------------------
// 8 K=64 sub-slices of fused weights, bf16, packed {B(k2), B(k2+4)} per uint2
__device__ uint2 g_Wb[8 * 128 * 16];
__device__ float g_partS[B_ * TILES * D_];
__device__ float g_partQ[B_ * TILES * D_];
__device__ float g_mean[B_ * D_];
__device__ float g_rstd[B_ * D_];

// ------------------------------- helpers ------------------------------------
__device__ __forceinline__ uint32_t pack2(float x, float y) {
    __nv_bfloat162 h = __floats2bfloat162_rn(x, y);
    return *reinterpret_cast<uint32_t*>(&h);
}
__device__ __forceinline__ void split2(float x, float y, uint32_t& hi, uint32_t& lo) {
    __nv_bfloat162 h = __floats2bfloat162_rn(x, y);
    float lx = x - __bfloat162float(h.x);
    float ly = y - __bfloat162float(h.y);
    __nv_bfloat162 l = __floats2bfloat162_rn(lx, ly);
    hi = *reinterpret_cast<uint32_t*>(&h);
    lo = *reinterpret_cast<uint32_t*>(&l);
}

__device__ __forceinline__ void mma16816(float (&c)[4],
                                         uint32_t a0, uint32_t a1, uint32_t a2, uint32_t a3,
                                         uint32_t b0, uint32_t b1) {
    asm("mma.sync.aligned.m16n8k16.row.col.f32.bf16.bf16.f32 "
        "{%0,%1,%2,%3}, {%4,%5,%6,%7}, {%8,%9}, {%0,%1,%2,%3};"
        : "+f"(c[0]), "+f"(c[1]), "+f"(c[2]), "+f"(c[3])
        : "r"(a0), "r"(a1), "r"(a2), "r"(a3), "r"(b0), "r"(b1));
}

__device__ __forceinline__ void cp16(void* dst_smem, const void* src) {
    unsigned sa = (unsigned)__cvta_generic_to_shared(dst_smem);
    asm volatile("cp.async.cg.shared.global [%0], [%1], 16;\n" :: "r"(sa), "l"(src));
}
__device__ __forceinline__ void cp_commit() { asm volatile("cp.async.commit_group;\n"); }
template <int N>
__device__ __forceinline__ void cp_wait() { asm volatile("cp.async.wait_group %0;\n" :: "n"(N)); }

// -------------------------- fused weight prep --------------------------------
// row[512] = [wc1 | wc2@wl | wc2@wr | wff]; pack to 8 K=64 sub-slices of bf16
__global__ void prep_kernel(const float* __restrict__ w_comb,
                            const float* __restrict__ w_left,
                            const float* __restrict__ w_right,
                            const float* __restrict__ w_ff) {
    __shared__ float row[512];
    int n = blockIdx.x, k = threadIdx.x;          // 128 x 128
    row[k] = w_comb[n * 256 + k];
    float a1 = 0.f, a2 = 0.f;
    for (int m = 0; m < 128; ++m) {
        float wc = w_comb[n * 256 + 128 + m];
        a1 = fmaf(wc, w_left[m * 128 + k], a1);
        a2 = fmaf(wc, w_right[m * 128 + k], a2);
    }
    row[128 + k] = a1;
    row[256 + k] = a2;
    row[384 + k] = w_ff[n * 128 + k];
    __syncthreads();
    // pack: thread k -> (ss = k>>4, e = k&15); e = c*4+cq
    const int ss = k >> 4, e = k & 15;
    const int c = e >> 2, cq = e & 3;
    const int base = ss * 64;
    const int i0 = base + (c * 8 + cq) * 2;
    const int i1 = base + (c * 8 + cq + 4) * 2;
    uint2 w;
    w.x = pack2(row[i0], row[i0 + 1]);
    w.y = pack2(row[i1], row[i1 + 1]);
    g_Wb[(ss * 128 + n) * 16 + e] = w;
}

// --------------------------- main fused kernel -------------------------------
// smem: 4 B-buffers [128][SPU] uint2 | sBc[128] | sBf[128] | sS[8*128] | sQ[8*128]
#define WBUF_BYTES (128 * SPU * 8)                      // 20480
#define SMEM_BYTES (4 * WBUF_BYTES + 1024 + 8192)       // 91136

__device__ __forceinline__ void copy_slice_async(uint2* dst, int ss, int tid) {
    const uint2* src = g_Wb + ss * 128 * 16;
#pragma unroll
    for (int i = tid; i < 1024; i += 256) {             // 1024 x 16B = 16KB
        int n = i >> 3, ee = (i & 7) * 2;
        cp16(dst + n * SPU + ee, src + n * 16 + ee);
    }
    cp_commit();
}

// one K=64 GEMM sub-slice over gathered rows p0/p1 (2-term split-A)
__device__ __forceinline__ void compute_slice(const uint2* __restrict__ sW,
                                              const float* __restrict__ p0,
                                              const float* __restrict__ p1,
                                              int cq, int g, float (&acc)[16][4]) {
    float2 n0a = *reinterpret_cast<const float2*>(p0 + cq * 2);
    float2 n0b = *reinterpret_cast<const float2*>(p0 + cq * 2 + 8);
    float2 n1a = *reinterpret_cast<const float2*>(p1 + cq * 2);
    float2 n1b = *reinterpret_cast<const float2*>(p1 + cq * 2 + 8);
#pragma unroll
    for (int c = 0; c < 4; ++c) {
        float2 x0a = n0a, x0b = n0b, x1a = n1a, x1b = n1b;
        if (c < 3) {
            const int kc = (c + 1) * 16 + cq * 2;
            n0a = *reinterpret_cast<const float2*>(p0 + kc);
            n0b = *reinterpret_cast<const float2*>(p0 + kc + 8);
            n1a = *reinterpret_cast<const float2*>(p1 + kc);
            n1b = *reinterpret_cast<const float2*>(p1 + kc + 8);
        }
        uint32_t ah0, al0, ah1, al1, ah2, al2, ah3, al3;
        split2(x0a.x, x0a.y, ah0, al0);
        split2(x1a.x, x1a.y, ah1, al1);
        split2(x0b.x, x0b.y, ah2, al2);
        split2(x1b.x, x1b.y, ah3, al3);
        const int e = c * 4 + cq;
#pragma unroll
        for (int j = 0; j < 16; ++j) {
            const int col = j * 8 + g;
            uint2 w = sW[col * SPU + e];
            mma16816(acc[j], ah0, ah1, ah2, ah3, w.x, w.y);
            mma16816(acc[j], al0, al1, al2, al3, w.x, w.y);
        }
    }
}

__global__ void __launch_bounds__(256, 2)
main_kernel(const int* __restrict__ sn, const float* __restrict__ emb,
            const float* __restrict__ b_comb, const float* __restrict__ b_ff,
            float* __restrict__ out) {
    extern __shared__ char smem[];
    uint2* sb0 = reinterpret_cast<uint2*>(smem);
    uint2* sb1 = reinterpret_cast<uint2*>(smem + WBUF_BYTES);
    uint2* sb2 = reinterpret_cast<uint2*>(smem + 2 * WBUF_BYTES);
    uint2* sb3 = reinterpret_cast<uint2*>(smem + 3 * WBUF_BYTES);
    float* sBc = reinterpret_cast<float*>(smem + 4 * WBUF_BYTES);
    float* sBf = sBc + 128;
    float* sS  = sBf + 128;
    float* sQ  = sS + 8 * 128;

    const int tid  = threadIdx.x;
    const int w    = tid >> 5;
    const int lane = tid & 31;
    const int g    = lane >> 2;
    const int cq   = lane & 3;
    const int b    = blockIdx.y;

    const int tokBase = blockIdx.x * 128 + w * 16;
    const int t0 = tokBase + g;
    const int t1 = t0 + 8;
    const bool v0 = (t0 < N_), v1 = (t1 < N_);
    const int t0c = v0 ? t0 : (N_ - 1);
    const int t1c = v1 ? t1 : (N_ - 1);

    const float* emb_b = emb + (size_t)b * NP1 * D_;
    const int*   sn_b  = sn  + (size_t)b * N_ * 2;

    // stage first 4 sub-slices up front (groups G0..G3)
    copy_slice_async(sb0, 0, tid);
    copy_slice_async(sb1, 1, tid);
    copy_slice_async(sb2, 2, tid);
    copy_slice_async(sb3, 3, tid);

    const int li0 = sn_b[t0c * 2],     li1 = sn_b[t1c * 2];
    const int ri0 = sn_b[t0c * 2 + 1], ri1 = sn_b[t1c * 2 + 1];
    const float* c0p = emb_b + (size_t)(1 + t0c) * D_;
    const float* c1p = emb_b + (size_t)(1 + t1c) * D_;
    const float* l0p = emb_b + (size_t)li0 * D_;
    const float* l1p = emb_b + (size_t)li1 * D_;
    const float* r0p = emb_b + (size_t)ri0 * D_;
    const float* r1p = emb_b + (size_t)ri1 * D_;

    if (tid < 128) sBc[tid] = b_comb[tid];
    else           sBf[tid - 128] = b_ff[tid - 128];

    float acc[16][4];
#pragma unroll
    for (int j = 0; j < 16; ++j) { acc[j][0]=0.f; acc[j][1]=0.f; acc[j][2]=0.f; acc[j][3]=0.f; }

    // ---- Stage 1: 6 K=64 sub-slices through 4 buffers ----
    cp_wait<3>(); __syncthreads();                       // G0 done
    compute_slice(sb0, c0p, c1p, cq, g, acc);            // ss0: cust[0:64]
    cp_wait<2>(); __syncthreads();                       // G1 done; all past sb0
    copy_slice_async(sb0, 4, tid);                       // G4: right[0:64] weights
    compute_slice(sb1, c0p + 64, c1p + 64, cq, g, acc);  // ss1
    cp_wait<2>(); __syncthreads();                       // G2 done
    copy_slice_async(sb1, 5, tid);                       // G5
    compute_slice(sb2, l0p, l1p, cq, g, acc);            // ss2
    cp_wait<2>(); __syncthreads();                       // G3 done
    copy_slice_async(sb2, 6, tid);                       // G6: wff[0:64]
    compute_slice(sb3, l0p + 64, l1p + 64, cq, g, acc);  // ss3
    cp_wait<2>(); __syncthreads();                       // G4 done
    copy_slice_async(sb3, 7, tid);                       // G7: wff[64:128]
    compute_slice(sb0, r0p, r1p, cq, g, acc);            // ss4
    cp_wait<1>(); __syncthreads();                       // G5 done
    compute_slice(sb1, r0p + 64, r1p + 64, cq, g, acc);  // ss5

    // bias + relu
#pragma unroll
    for (int j = 0; j < 16; ++j) {
        const int n0 = j * 8 + cq * 2;
        acc[j][0] = fmaxf(acc[j][0] + sBc[n0],     0.f);
        acc[j][1] = fmaxf(acc[j][1] + sBc[n0 + 1], 0.f);
        acc[j][2] = fmaxf(acc[j][2] + sBc[n0],     0.f);
        acc[j][3] = fmaxf(acc[j][3] + sBc[n0 + 1], 0.f);
    }
    cp_wait<0>(); __syncthreads();                       // G6,G7 done (sb2, sb3 = wff)

    // ---- Stage 2 + fused epilogue, j-blocks of 4 ----
    float* out_b = out + ((size_t)b * NP1 + 1) * D_;

#pragma unroll
    for (int jb = 0; jb < 4; ++jb) {
        float a2[4][4];
#pragma unroll
        for (int jj = 0; jj < 4; ++jj) { a2[jj][0]=0.f; a2[jj][1]=0.f; a2[jj][2]=0.f; a2[jj][3]=0.f; }
#pragma unroll
        for (int c = 0; c < 8; ++c) {
            const uint2* sWc = (c < 4) ? sb2 : sb3;
            uint32_t ah0, al0, ah1, al1, ah2, al2, ah3, al3;
            split2(acc[2*c][0],   acc[2*c][1],   ah0, al0);
            split2(acc[2*c][2],   acc[2*c][3],   ah1, al1);
            split2(acc[2*c+1][0], acc[2*c+1][1], ah2, al2);
            split2(acc[2*c+1][2], acc[2*c+1][3], ah3, al3);
            const int e = (c & 3) * 4 + cq;
#pragma unroll
            for (int jj = 0; jj < 4; ++jj) {
                const int col = (jb * 4 + jj) * 8 + g;
                uint2 ww = sWc[col * SPU + e];
                mma16816(a2[jj], ah0, ah1, ah2, ah3, ww.x, ww.y);
                mma16816(a2[jj], al0, al1, al2, al3, ww.x, ww.y);
            }
        }
        // epilogue for these 4 j's
#pragma unroll
        for (int jj = 0; jj < 4; ++jj) {
            const int f = (jb * 4 + jj) * 8 + cq * 2;
            float2 cu0 = *reinterpret_cast<const float2*>(c0p + f);
            float2 cu1 = *reinterpret_cast<const float2*>(c1p + f);
            float add0 = cu0.x + a2[jj][0] + sBf[f];
            float add1 = cu0.y + a2[jj][1] + sBf[f + 1];
            float add2 = cu1.x + a2[jj][2] + sBf[f];
            float add3 = cu1.y + a2[jj][3] + sBf[f + 1];
            if (v0) { *reinterpret_cast<float2*>(out_b + (size_t)t0 * D_ + f) = make_float2(add0, add1); }
            else { add0 = 0.f; add1 = 0.f; }
            if (v1) { *reinterpret_cast<float2*>(out_b + (size_t)t1 * D_ + f) = make_float2(add2, add3); }
            else { add2 = 0.f; add3 = 0.f; }

            float s0 = add0 + add2, s1 = add1 + add3;
            float q0 = add0 * add0 + add2 * add2, q1 = add1 * add1 + add3 * add3;
#pragma unroll
            for (int o = 4; o < 32; o <<= 1) {
                s0 += __shfl_xor_sync(0xffffffffu, s0, o);
                s1 += __shfl_xor_sync(0xffffffffu, s1, o);
                q0 += __shfl_xor_sync(0xffffffffu, q0, o);
                q1 += __shfl_xor_sync(0xffffffffu, q1, o);
            }
            if (lane < 4) {
                sS[w * 128 + f] = s0; sS[w * 128 + f + 1] = s1;
                sQ[w * 128 + f] = q0; sQ[w * 128 + f + 1] = q1;
            }
        }
    }
    __syncthreads();
    if (tid < 128) {
        float S = 0.f, Q = 0.f;
#pragma unroll
        for (int ww = 0; ww < 8; ++ww) { S += sS[ww * 128 + tid]; Q += sQ[ww * 128 + tid]; }
        const size_t slot = ((size_t)b * TILES + blockIdx.x) * D_ + tid;
        g_partS[slot] = S;
        g_partQ[slot] = Q;
    }
}

// --------------------------- LN stats + normalize ----------------------------
__global__ void stats_kernel() {
    int b = blockIdx.x, f = threadIdx.x;
    float S = 0.f, Q = 0.f;
    for (int c = 0; c < TILES; ++c) {
        S += g_partS[((size_t)b * TILES + c) * D_ + f];
        Q += g_partQ[((size_t)b * TILES + c) * D_ + f];
    }
    float mean = S * (1.0f / N_);
    float var  = Q * (1.0f / N_) - mean * mean;
    g_mean[b * D_ + f] = mean;
    g_rstd[b * D_ + f] = rsqrtf(var + 1e-5f);
}

__global__ void __launch_bounds__(256)
norm_kernel(const float* __restrict__ norm_w, const float* __restrict__ norm_b,
            float* __restrict__ out) {
    int v = blockIdx.x * 256 + threadIdx.x;        // float4 index over 64*5000*32
    int b = v / (N_ * 32);
    int r = v - b * (N_ * 32);
    int t = r >> 5;
    int f4 = (r & 31) * 4;
    size_t idx = ((size_t)b * NP1 + 1 + t) * D_ + f4;
    float4 x  = *reinterpret_cast<float4*>(out + idx);
    float4 m  = *reinterpret_cast<const float4*>(g_mean + b * D_ + f4);
    float4 s  = *reinterpret_cast<const float4*>(g_rstd + b * D_ + f4);
    float4 ww = *reinterpret_cast<const float4*>(norm_w + f4);
    float4 bb = *reinterpret_cast<const float4*>(norm_b + f4);
    x.x = (x.x - m.x) * s.x * ww.x + bb.x;
    x.y = (x.y - m.y) * s.y * ww.y + bb.y;
    x.z = (x.z - m.z) * s.z * ww.z + bb.z;
    x.w = (x.w - m.w) * s.w * ww.w + bb.w;
    *reinterpret_cast<float4*>(out + idx) = x;
}

// ------------------------------- launcher ------------------------------------
extern "C" void kernel_launch(void* const* d_in, const int* in_sizes, int n_in,
                              void* d_out, int out_size) {
    int i0 = 0;
    for (int i = 0; i < n_in; ++i) if (in_sizes[i] == B_ * N_ * 2) { i0 = i; break; }
    const int*   sn      = (const int*)d_in[i0];
    const float* emb     = (const float*)d_in[i0 + 1];
    const float* w_left  = (const float*)d_in[i0 + 2];
    const float* w_right = (const float*)d_in[i0 + 3];
    const float* w_comb  = (const float*)d_in[i0 + 4];
    const float* b_comb  = (const float*)d_in[i0 + 5];
    const float* w_ff    = (const float*)d_in[i0 + 6];
    const float* b_ff    = (const float*)d_in[i0 + 7];
    const float* norm_w  = (const float*)d_in[i0 + 8];
    const float* norm_b  = (const float*)d_in[i0 + 9];
    float* out = (float*)d_out;

    cudaFuncSetAttribute(main_kernel, cudaFuncAttributeMaxDynamicSharedMemorySize, SMEM_BYTES);

    // depot row (token 0) passthrough
    cudaMemcpy2DAsync(out, (size_t)NP1 * D_ * sizeof(float),
                      emb, (size_t)NP1 * D_ * sizeof(float),
                      D_ * sizeof(float), B_, cudaMemcpyDeviceToDevice);

    prep_kernel<<<128, 128>>>(w_comb, w_left, w_right, w_ff);
    main_kernel<<<dim3(TILES, B_), 256, SMEM_BYTES>>>(sn, emb, b_comb, b_ff, out);
    stats_kernel<<<B_, 128>>>();
    norm_kernel<<<B_ * N_ * 32 / 256, 256>>>(norm_w, norm_b, out);
}

// round 8
// speedup vs baseline: 2.1970x; 1.1513x over previous
#include <cuda_runtime.h>
#include <cuda_fp16.h>
#include <cstdint>

#define B_   64
#define N_   5000
#define NP1  5001
#define D_   128
#define TILES 40
#define SPU  20     // smem B row stride in uint2 (==4 mod 16 -> conflict-free LDS.64)

// ------------------------- device scratch (no allocs) -----------------------
// 8 K=64 sub-slices of fused weights, fp16, packed {B(k2), B(k2+4)} per uint2
__device__ uint2 g_Wb[8 * 128 * 16];
__device__ float g_partS[B_ * TILES * D_];
__device__ float g_partQ[B_ * TILES * D_];
__device__ float g_mean[B_ * D_];
__device__ float g_rstd[B_ * D_];

// ------------------------------- helpers ------------------------------------
__device__ __forceinline__ uint32_t cvt2h(float x, float y) {
    __half2 h = __floats2half2_rn(x, y);
    return *reinterpret_cast<uint32_t*>(&h);
}

__device__ __forceinline__ void mma16816(float (&c)[4],
                                         uint32_t a0, uint32_t a1, uint32_t a2, uint32_t a3,
                                         uint32_t b0, uint32_t b1) {
    asm("mma.sync.aligned.m16n8k16.row.col.f32.f16.f16.f32 "
        "{%0,%1,%2,%3}, {%4,%5,%6,%7}, {%8,%9}, {%0,%1,%2,%3};"
        : "+f"(c[0]), "+f"(c[1]), "+f"(c[2]), "+f"(c[3])
        : "r"(a0), "r"(a1), "r"(a2), "r"(a3), "r"(b0), "r"(b1));
}

__device__ __forceinline__ void cp16(void* dst_smem, const void* src) {
    unsigned sa = (unsigned)__cvta_generic_to_shared(dst_smem);
    asm volatile("cp.async.cg.shared.global [%0], [%1], 16;\n" :: "r"(sa), "l"(src));
}
__device__ __forceinline__ void cp_commit() { asm volatile("cp.async.commit_group;\n"); }
template <int N>
__device__ __forceinline__ void cp_wait() { asm volatile("cp.async.wait_group %0;\n" :: "n"(N)); }

// -------------------------- fused weight prep --------------------------------
// row[512] = [wc1 | wc2@wl | wc2@wr | wff]; pack to 8 K=64 sub-slices of fp16
__global__ void prep_kernel(const float* __restrict__ w_comb,
                            const float* __restrict__ w_left,
                            const float* __restrict__ w_right,
                            const float* __restrict__ w_ff) {
    __shared__ float row[512];
    int n = blockIdx.x, k = threadIdx.x;          // 128 x 128
    row[k] = w_comb[n * 256 + k];
    float a1 = 0.f, a2 = 0.f;
    for (int m = 0; m < 128; ++m) {
        float wc = w_comb[n * 256 + 128 + m];
        a1 = fmaf(wc, w_left[m * 128 + k], a1);
        a2 = fmaf(wc, w_right[m * 128 + k], a2);
    }
    row[128 + k] = a1;
    row[256 + k] = a2;
    row[384 + k] = w_ff[n * 128 + k];
    __syncthreads();
    // pack: thread k -> (ss = k>>4, e = k&15); e = c*4+cq
    const int ss = k >> 4, e = k & 15;
    const int c = e >> 2, cq = e & 3;
    const int base = ss * 64;
    const int i0 = base + (c * 8 + cq) * 2;
    const int i1 = base + (c * 8 + cq + 4) * 2;
    uint2 w;
    w.x = cvt2h(row[i0], row[i0 + 1]);
    w.y = cvt2h(row[i1], row[i1 + 1]);
    g_Wb[(ss * 128 + n) * 16 + e] = w;
}

// --------------------------- main fused kernel -------------------------------
// smem: 4 B-buffers [128][SPU] uint2 | sBc[128] | sBf[128] | sS[8*128] | sQ[8*128]
#define WBUF_BYTES (128 * SPU * 8)                      // 20480
#define SMEM_BYTES (4 * WBUF_BYTES + 1024 + 8192)       // 91136

__device__ __forceinline__ void copy_slice_async(uint2* dst, int ss, int tid) {
    const uint2* src = g_Wb + ss * 128 * 16;
#pragma unroll
    for (int i = tid; i < 1024; i += 256) {             // 1024 x 16B = 16KB
        int n = i >> 3, ee = (i & 7) * 2;
        cp16(dst + n * SPU + ee, src + n * 16 + ee);
    }
    cp_commit();
}

// one K=64 GEMM sub-slice over gathered rows p0/p1 (single fp16 term)
__device__ __forceinline__ void compute_slice(const uint2* __restrict__ sW,
                                              const float* __restrict__ p0,
                                              const float* __restrict__ p1,
                                              int cq, int g, float (&acc)[16][4]) {
    float2 n0a = *reinterpret_cast<const float2*>(p0 + cq * 2);
    float2 n0b = *reinterpret_cast<const float2*>(p0 + cq * 2 + 8);
    float2 n1a = *reinterpret_cast<const float2*>(p1 + cq * 2);
    float2 n1b = *reinterpret_cast<const float2*>(p1 + cq * 2 + 8);
#pragma unroll
    for (int c = 0; c < 4; ++c) {
        float2 x0a = n0a, x0b = n0b, x1a = n1a, x1b = n1b;
        if (c < 3) {
            const int kc = (c + 1) * 16 + cq * 2;
            n0a = *reinterpret_cast<const float2*>(p0 + kc);
            n0b = *reinterpret_cast<const float2*>(p0 + kc + 8);
            n1a = *reinterpret_cast<const float2*>(p1 + kc);
            n1b = *reinterpret_cast<const float2*>(p1 + kc + 8);
        }
        const uint32_t a0 = cvt2h(x0a.x, x0a.y);
        const uint32_t a1 = cvt2h(x1a.x, x1a.y);
        const uint32_t a2 = cvt2h(x0b.x, x0b.y);
        const uint32_t a3 = cvt2h(x1b.x, x1b.y);
        const int e = c * 4 + cq;
#pragma unroll
        for (int j = 0; j < 16; ++j) {
            const int col = j * 8 + g;
            uint2 w = sW[col * SPU + e];
            mma16816(acc[j], a0, a1, a2, a3, w.x, w.y);
        }
    }
}

__global__ void __launch_bounds__(256, 2)
main_kernel(const int* __restrict__ sn, const float* __restrict__ emb,
            const float* __restrict__ b_comb, const float* __restrict__ b_ff,
            float* __restrict__ out) {
    extern __shared__ char smem[];
    uint2* sb0 = reinterpret_cast<uint2*>(smem);
    uint2* sb1 = reinterpret_cast<uint2*>(smem + WBUF_BYTES);
    uint2* sb2 = reinterpret_cast<uint2*>(smem + 2 * WBUF_BYTES);
    uint2* sb3 = reinterpret_cast<uint2*>(smem + 3 * WBUF_BYTES);
    float* sBc = reinterpret_cast<float*>(smem + 4 * WBUF_BYTES);
    float* sBf = sBc + 128;
    float* sS  = sBf + 128;
    float* sQ  = sS + 8 * 128;

    const int tid  = threadIdx.x;
    const int w    = tid >> 5;
    const int lane = tid & 31;
    const int g    = lane >> 2;
    const int cq   = lane & 3;
    const int b    = blockIdx.y;

    const int tokBase = blockIdx.x * 128 + w * 16;
    const int t0 = tokBase + g;
    const int t1 = t0 + 8;
    const bool v0 = (t0 < N_), v1 = (t1 < N_);
    const int t0c = v0 ? t0 : (N_ - 1);
    const int t1c = v1 ? t1 : (N_ - 1);

    const float* emb_b = emb + (size_t)b * NP1 * D_;
    const int*   sn_b  = sn  + (size_t)b * N_ * 2;

    // stage first 4 sub-slices up front (groups G0..G3)
    copy_slice_async(sb0, 0, tid);
    copy_slice_async(sb1, 1, tid);
    copy_slice_async(sb2, 2, tid);
    copy_slice_async(sb3, 3, tid);

    const int li0 = sn_b[t0c * 2],     li1 = sn_b[t1c * 2];
    const int ri0 = sn_b[t0c * 2 + 1], ri1 = sn_b[t1c * 2 + 1];
    const float* c0p = emb_b + (size_t)(1 + t0c) * D_;
    const float* c1p = emb_b + (size_t)(1 + t1c) * D_;
    const float* l0p = emb_b + (size_t)li0 * D_;
    const float* l1p = emb_b + (size_t)li1 * D_;
    const float* r0p = emb_b + (size_t)ri0 * D_;
    const float* r1p = emb_b + (size_t)ri1 * D_;

    if (tid < 128) sBc[tid] = b_comb[tid];
    else           sBf[tid - 128] = b_ff[tid - 128];

    float acc[16][4];
#pragma unroll
    for (int j = 0; j < 16; ++j) { acc[j][0]=0.f; acc[j][1]=0.f; acc[j][2]=0.f; acc[j][3]=0.f; }

    // ---- Stage 1: 6 K=64 sub-slices through 4 buffers ----
    cp_wait<3>(); __syncthreads();                       // G0 done
    compute_slice(sb0, c0p, c1p, cq, g, acc);            // ss0: cust[0:64]
    cp_wait<2>(); __syncthreads();                       // G1 done; all past sb0
    copy_slice_async(sb0, 4, tid);                       // G4: right[0:64]
    compute_slice(sb1, c0p + 64, c1p + 64, cq, g, acc);  // ss1
    cp_wait<2>(); __syncthreads();                       // G2 done
    copy_slice_async(sb1, 5, tid);                       // G5
    compute_slice(sb2, l0p, l1p, cq, g, acc);            // ss2
    cp_wait<2>(); __syncthreads();                       // G3 done
    copy_slice_async(sb2, 6, tid);                       // G6: wff[0:64]
    compute_slice(sb3, l0p + 64, l1p + 64, cq, g, acc);  // ss3
    cp_wait<2>(); __syncthreads();                       // G4 done
    copy_slice_async(sb3, 7, tid);                       // G7: wff[64:128]
    compute_slice(sb0, r0p, r1p, cq, g, acc);            // ss4
    cp_wait<1>(); __syncthreads();                       // G5 done
    compute_slice(sb1, r0p + 64, r1p + 64, cq, g, acc);  // ss5

    // bias + relu
#pragma unroll
    for (int j = 0; j < 16; ++j) {
        const int n0 = j * 8 + cq * 2;
        acc[j][0] = fmaxf(acc[j][0] + sBc[n0],     0.f);
        acc[j][1] = fmaxf(acc[j][1] + sBc[n0 + 1], 0.f);
        acc[j][2] = fmaxf(acc[j][2] + sBc[n0],     0.f);
        acc[j][3] = fmaxf(acc[j][3] + sBc[n0 + 1], 0.f);
    }
    cp_wait<0>(); __syncthreads();                       // G6,G7 done (sb2, sb3 = wff)

    // ---- Stage 2 + fused epilogue, j-blocks of 4 ----
    float* out_b = out + ((size_t)b * NP1 + 1) * D_;

#pragma unroll
    for (int jb = 0; jb < 4; ++jb) {
        float a2[4][4];
#pragma unroll
        for (int jj = 0; jj < 4; ++jj) { a2[jj][0]=0.f; a2[jj][1]=0.f; a2[jj][2]=0.f; a2[jj][3]=0.f; }
#pragma unroll
        for (int c = 0; c < 8; ++c) {
            const uint2* sWc = (c < 4) ? sb2 : sb3;
            const uint32_t h0 = cvt2h(acc[2*c][0],   acc[2*c][1]);
            const uint32_t h1 = cvt2h(acc[2*c][2],   acc[2*c][3]);
            const uint32_t h2 = cvt2h(acc[2*c+1][0], acc[2*c+1][1]);
            const uint32_t h3 = cvt2h(acc[2*c+1][2], acc[2*c+1][3]);
            const int e = (c & 3) * 4 + cq;
#pragma unroll
            for (int jj = 0; jj < 4; ++jj) {
                const int col = (jb * 4 + jj) * 8 + g;
                uint2 ww = sWc[col * SPU + e];
                mma16816(a2[jj], h0, h1, h2, h3, ww.x, ww.y);
            }
        }
        // epilogue for these 4 j's
#pragma unroll
        for (int jj = 0; jj < 4; ++jj) {
            const int f = (jb * 4 + jj) * 8 + cq * 2;
            float2 cu0 = *reinterpret_cast<const float2*>(c0p + f);
            float2 cu1 = *reinterpret_cast<const float2*>(c1p + f);
            float add0 = cu0.x + a2[jj][0] + sBf[f];
            float add1 = cu0.y + a2[jj][1] + sBf[f + 1];
            float add2 = cu1.x + a2[jj][2] + sBf[f];
            float add3 = cu1.y + a2[jj][3] + sBf[f + 1];
            if (v0) { *reinterpret_cast<float2*>(out_b + (size_t)t0 * D_ + f) = make_float2(add0, add1); }
            else { add0 = 0.f; add1 = 0.f; }
            if (v1) { *reinterpret_cast<float2*>(out_b + (size_t)t1 * D_ + f) = make_float2(add2, add3); }
            else { add2 = 0.f; add3 = 0.f; }

            float s0 = add0 + add2, s1 = add1 + add3;
            float q0 = add0 * add0 + add2 * add2, q1 = add1 * add1 + add3 * add3;
#pragma unroll
            for (int o = 4; o < 32; o <<= 1) {
                s0 += __shfl_xor_sync(0xffffffffu, s0, o);
                s1 += __shfl_xor_sync(0xffffffffu, s1, o);
                q0 += __shfl_xor_sync(0xffffffffu, q0, o);
                q1 += __shfl_xor_sync(0xffffffffu, q1, o);
            }
            if (lane < 4) {
                sS[w * 128 + f] = s0; sS[w * 128 + f + 1] = s1;
                sQ[w * 128 + f] = q0; sQ[w * 128 + f + 1] = q1;
            }
        }
    }
    __syncthreads();
    if (tid < 128) {
        float S = 0.f, Q = 0.f;
#pragma unroll
        for (int ww = 0; ww < 8; ++ww) { S += sS[ww * 128 + tid]; Q += sQ[ww * 128 + tid]; }
        const size_t slot = ((size_t)b * TILES + blockIdx.x) * D_ + tid;
        g_partS[slot] = S;
        g_partQ[slot] = Q;
    }
}

// --------------------------- LN stats + normalize ----------------------------
__global__ void stats_kernel() {
    int b = blockIdx.x, f = threadIdx.x;
    float S = 0.f, Q = 0.f;
    for (int c = 0; c < TILES; ++c) {
        S += g_partS[((size_t)b * TILES + c) * D_ + f];
        Q += g_partQ[((size_t)b * TILES + c) * D_ + f];
    }
    float mean = S * (1.0f / N_);
    float var  = Q * (1.0f / N_) - mean * mean;
    g_mean[b * D_ + f] = mean;
    g_rstd[b * D_ + f] = rsqrtf(var + 1e-5f);
}

__global__ void __launch_bounds__(256)
norm_kernel(const float* __restrict__ norm_w, const float* __restrict__ norm_b,
            float* __restrict__ out) {
    int v = blockIdx.x * 256 + threadIdx.x;        // float4 index over 64*5000*32
    int b = v / (N_ * 32);
    int r = v - b * (N_ * 32);
    int t = r >> 5;
    int f4 = (r & 31) * 4;
    size_t idx = ((size_t)b * NP1 + 1 + t) * D_ + f4;
    float4 x  = *reinterpret_cast<float4*>(out + idx);
    float4 m  = *reinterpret_cast<const float4*>(g_mean + b * D_ + f4);
    float4 s  = *reinterpret_cast<const float4*>(g_rstd + b * D_ + f4);
    float4 ww = *reinterpret_cast<const float4*>(norm_w + f4);
    float4 bb = *reinterpret_cast<const float4*>(norm_b + f4);
    x.x = (x.x - m.x) * s.x * ww.x + bb.x;
    x.y = (x.y - m.y) * s.y * ww.y + bb.y;
    x.z = (x.z - m.z) * s.z * ww.z + bb.z;
    x.w = (x.w - m.w) * s.w * ww.w + bb.w;
    *reinterpret_cast<float4*>(out + idx) = x;
}

// ------------------------------- launcher ------------------------------------
extern "C" void kernel_launch(void* const* d_in, const int* in_sizes, int n_in,
                              void* d_out, int out_size) {
    int i0 = 0;
    for (int i = 0; i < n_in; ++i) if (in_sizes[i] == B_ * N_ * 2) { i0 = i; break; }
    const int*   sn      = (const int*)d_in[i0];
    const float* emb     = (const float*)d_in[i0 + 1];
    const float* w_left  = (const float*)d_in[i0 + 2];
    const float* w_right = (const float*)d_in[i0 + 3];
    const float* w_comb  = (const float*)d_in[i0 + 4];
    const float* b_comb  = (const float*)d_in[i0 + 5];
    const float* w_ff    = (const float*)d_in[i0 + 6];
    const float* b_ff    = (const float*)d_in[i0 + 7];
    const float* norm_w  = (const float*)d_in[i0 + 8];
    const float* norm_b  = (const float*)d_in[i0 + 9];
    float* out = (float*)d_out;

    cudaFuncSetAttribute(main_kernel, cudaFuncAttributeMaxDynamicSharedMemorySize, SMEM_BYTES);

    // depot row (token 0) passthrough
    cudaMemcpy2DAsync(out, (size_t)NP1 * D_ * sizeof(float),
                      emb, (size_t)NP1 * D_ * sizeof(float),
                      D_ * sizeof(float), B_, cudaMemcpyDeviceToDevice);

    prep_kernel<<<128, 128>>>(w_comb, w_left, w_right, w_ff);
    main_kernel<<<dim3(TILES, B_), 256, SMEM_BYTES>>>(sn, emb, b_comb, b_ff, out);
    stats_kernel<<<B_, 128>>>();
    norm_kernel<<<B_ * N_ * 32 / 256, 256>>>(norm_w, norm_b, out);
}